// round 15
// baseline (speedup 1.0000x reference)
#include <cuda_runtime.h>
#include <cuda_bf16.h>
#include <stdint.h>
#include <math.h>

#define NBATCH 4
#define NFQ    300
#define QDIM   512
#define HIDDEN 512
#define NHEADS 8
#define HD     64
#define NPIX   6400
#define NORMF  0.125f
#define MROWS  (NBATCH*NFQ)
#define OROWS  (NFQ*NHEADS)          // 2400
#define CBLK_PER_BATCH 1200          // 8 heads * 3 mtiles * 50 ntiles
#define TILE_B 16384
#define TILE_E 8192

// ---------------- static device scratch (pre-swizzled tile layouts) ----------------
__device__ __align__(128) __nv_bfloat16 g_kwT_hi[4*8*TILE_E];
__device__ __align__(128) __nv_bfloat16 g_kwT_lo[4*8*TILE_E];
__device__ __align__(128) __nv_bfloat16 g_ktT_hi[(size_t)4*50*8*TILE_E];
__device__ __align__(128) __nv_bfloat16 g_ktT_lo[(size_t)4*50*8*TILE_E];
__device__ __align__(128) __nv_bfloat16 g_qhtT_hi[4*8*3*TILE_E];
__device__ __align__(128) __nv_bfloat16 g_qhtT_lo[4*8*3*TILE_E];
__device__ float g_pmax[NBATCH*CBLK_PER_BATCH];
__device__ float g_psum[NBATCH*CBLK_PER_BATCH];
__device__ float g_bscale[NBATCH*CBLK_PER_BATCH];

// ---------------- fused-kernel smem layout ----------------
// Phase 1 (kproj mainloop): 3 stages x 32KB at 0 / 32K / 64K
// Phase 2/3: B tiles (aliases stages 0,1):
//   head h: hi at h*32768, lo at h*32768+16384   (0..64K)
//   A bufs (alias stage 2): A0 at 65536 (Ah), A1 at 81920 (Al)
#define STAGE_SZ 32768u
#define STG(s)   ((uint32_t)(s) * STAGE_SZ)
#define A0_OFF  65536u
#define A1_OFF  81920u
#define KB_OFF  98304u                 // 512 B bias
#define MK_OFF  98816u                 // 512 B mask
#define RM_OFF  99328u                 // 1 KB
#define RS_OFF  100352u                // 1 KB
#define MB_OFF  101376u                // 5 mbarriers x 8 B
#define SMEM_SZ 101424u

// ---------------- ptx helpers ----------------
__device__ __forceinline__ uint32_t smem_u32(const void* p) {
    uint32_t a;
    asm("{ .reg .u64 t; cvta.to.shared.u64 t, %1; cvt.u32.u64 %0, t; }" : "=r"(a) : "l"(p));
    return a;
}
__device__ __forceinline__ void bulk_cp(uint32_t dst, const void* src, uint32_t bytes,
                                        uint32_t mbar) {
    asm volatile("cp.async.bulk.shared::cta.global.mbarrier::complete_tx::bytes "
                 "[%0], [%1], %2, [%3];"
                 :: "r"(dst), "l"(src), "r"(bytes), "r"(mbar) : "memory");
}
#define MBINIT(a,c) asm volatile("mbarrier.init.shared.b64 [%0], %1;" :: "r"(a), "r"(c) : "memory")
#define MBEXPECT(a,tx) asm volatile("mbarrier.arrive.expect_tx.shared.b64 _, [%0], %1;" :: "r"(a), "r"(tx) : "memory")
#define MBAR_WAIT(mbar, parity) do { \
    uint32_t _m = (mbar); uint32_t _p = (parity); uint32_t _done; \
    asm volatile("{\n\t.reg .pred p;\n\t" \
        "mbarrier.try_wait.parity.acquire.cta.shared::cta.b64 p, [%1], %2;\n\t" \
        "selp.b32 %0, 1, 0, p;\n\t}" : "=r"(_done) : "r"(_m), "r"(_p) : "memory"); \
    if (!_done) { \
        asm volatile("{\n\t.reg .pred P1;\n\t" \
            "WL_%=:\n\t" \
            "mbarrier.try_wait.parity.acquire.cta.shared::cta.b64 P1, [%0], %1, 0x989680;\n\t" \
            "@P1 bra.uni WD_%=;\n\t" \
            "bra.uni WL_%=;\n\t" \
            "WD_%=:\n\t}" :: "r"(_m), "r"(_p) : "memory"); \
    } \
} while(0)

__device__ __forceinline__ void ldm_x4(uint32_t& r0, uint32_t& r1, uint32_t& r2, uint32_t& r3,
                                       uint32_t addr) {
    asm volatile("ldmatrix.sync.aligned.m8n8.x4.shared.b16 {%0,%1,%2,%3}, [%4];"
                 : "=r"(r0), "=r"(r1), "=r"(r2), "=r"(r3) : "r"(addr));
}
__device__ __forceinline__ void mma_bf16(float* c, uint32_t a0, uint32_t a1, uint32_t a2,
                                         uint32_t a3, uint32_t b0, uint32_t b1) {
    asm volatile("mma.sync.aligned.m16n8k16.row.col.f32.bf16.bf16.f32 "
        "{%0,%1,%2,%3}, {%4,%5,%6,%7}, {%8,%9}, {%0,%1,%2,%3};"
        : "+f"(c[0]), "+f"(c[1]), "+f"(c[2]), "+f"(c[3])
        : "r"(a0), "r"(a1), "r"(a2), "r"(a3), "r"(b0), "r"(b1));
}
__device__ __forceinline__ uint32_t sw128(uint32_t off) { return off ^ ((off >> 3) & 0x70); }

__device__ __forceinline__ void split_bf16(float x, __nv_bfloat16& h, __nv_bfloat16& l) {
    h = __float2bfloat16(x);
    l = __float2bfloat16(x - __bfloat162float(h));
}

// ---- one 64-wide K chunk of 128x128 HMMA (warp tile 64x32, 8 warps) ----
__device__ __forceinline__ void compute_chunk(uint32_t aBase, uint32_t bBase,
                                              int wm, int wn, int lane,
                                              float acc[4][4][4]) {
#pragma unroll
    for (int kk = 0; kk < 64; kk += 16) {
        uint32_t a[4][4];
#pragma unroll
        for (int mf = 0; mf < 4; mf++) {
            int row  = wm*64 + mf*16 + (lane & 15);
            int kcol = kk + ((lane >> 4) << 3);
            uint32_t off = sw128((uint32_t)(row*128 + kcol*2));
            ldm_x4(a[mf][0], a[mf][1], a[mf][2], a[mf][3], aBase + off);
        }
        uint32_t b[4][2];
#pragma unroll
        for (int g = 0; g < 2; g++) {
            int nrow = wn*32 + g*16 + ((lane >> 4) << 3) + (lane & 7);
            int kcol = kk + (((lane >> 3) & 1) << 3);
            uint32_t off = sw128((uint32_t)(nrow*128 + kcol*2));
            uint32_t r0, r1, r2, r3;
            ldm_x4(r0, r1, r2, r3, bBase + off);
            b[g*2][0] = r0; b[g*2][1] = r1; b[g*2+1][0] = r2; b[g*2+1][1] = r3;
        }
#pragma unroll
        for (int mf = 0; mf < 4; mf++)
#pragma unroll
            for (int nf = 0; nf < 4; nf++)
                mma_bf16(acc[mf][nf], a[mf][0], a[mf][1], a[mf][2], a[mf][3],
                         b[nf][0], b[nf][1]);
    }
}

// ============================================================
// convert kw -> pre-swizzled tiles
// ============================================================
__global__ void kwconv_kernel(const float* __restrict__ kw) {
    int n8 = HIDDEN*QDIM/8;
    for (int i = blockIdx.x*blockDim.x + threadIdx.x; i < n8; i += gridDim.x*blockDim.x) {
        int e = i >> 6, dg = i & 63;
        int d0 = dg * 8;
        __align__(16) __nv_bfloat16 h8[8];
        __align__(16) __nv_bfloat16 l8[8];
#pragma unroll
        for (int j = 0; j < 8; j++)
            split_bf16(kw[(size_t)e*QDIM + d0 + j], h8[j], l8[j]);
        uint32_t tile = (uint32_t)(e >> 7)*8 + (d0 >> 6);
        uint32_t off = tile*TILE_B + sw128((uint32_t)((e & 127)*128 + (d0 & 63)*2));
        *(uint4*)((char*)g_kwT_hi + off) = *(uint4*)h8;
        *(uint4*)((char*)g_kwT_lo + off) = *(uint4*)l8;
    }
}

// ============================================================
// convert + transpose k -> pre-swizzled kt tiles
// ============================================================
__global__ void kconv_kernel(const float* __restrict__ kin) {
    __shared__ float tile[64][33];
    int b = blockIdx.z;
    int p0 = blockIdx.x*32, d0 = blockIdx.y*64;
    int tx = threadIdx.x, ty = threadIdx.y;
    const float* src = kin + ((size_t)b*QDIM + d0)*NPIX + p0;
#pragma unroll
    for (int i = 0; i < 8; i++)
        tile[ty + i*8][tx] = src[(size_t)(ty + i*8)*NPIX + tx];
    __syncthreads();
    int tid = ty*32 + tx;
    int pl = tid >> 3, dg = tid & 7;
    __align__(16) __nv_bfloat16 h8[8];
    __align__(16) __nv_bfloat16 l8[8];
#pragma unroll
    for (int j = 0; j < 8; j++)
        split_bf16(tile[dg*8 + j][pl], h8[j], l8[j]);
    int p = p0 + pl;
    uint32_t tl = (uint32_t)((b*50 + (p >> 7))*8 + (d0 >> 6));
    uint32_t off = tl*TILE_B + sw128((uint32_t)((p & 127)*128 + dg*16));
    *(uint4*)((char*)g_ktT_hi + off) = *(uint4*)h8;
    *(uint4*)((char*)g_ktT_lo + off) = *(uint4*)l8;
}

// ============================================================
// q projection (SIMT) -> pre-swizzled qht tiles
// ============================================================
__global__ void qproj_kernel(const float* __restrict__ q,
                             const float* __restrict__ qw,
                             const float* __restrict__ qb) {
    const int BM = 64, BN = 64, BK = 16;
    __shared__ float As[BK][BM];
    __shared__ float Bs[BK][BN];
    int t  = threadIdx.x;
    int tx = t & 15, ty = t >> 4;
    int m0 = blockIdx.y * BM;
    int n0 = blockIdx.x * BN;
    int lrow = t >> 2, lseg = t & 3;

    float acc[4][4] = {};
    for (int k0 = 0; k0 < QDIM; k0 += BK) {
        float4 av = make_float4(0.f, 0.f, 0.f, 0.f);
        int gm = m0 + lrow;
        if (gm < MROWS)
            av = *(const float4*)(q + (size_t)gm*QDIM + k0 + lseg*4);
        float4 bv = *(const float4*)(qw + (size_t)(n0 + lrow)*QDIM + k0 + lseg*4);
        __syncthreads();
        As[lseg*4+0][lrow]=av.x; As[lseg*4+1][lrow]=av.y;
        As[lseg*4+2][lrow]=av.z; As[lseg*4+3][lrow]=av.w;
        Bs[lseg*4+0][lrow]=bv.x; Bs[lseg*4+1][lrow]=bv.y;
        Bs[lseg*4+2][lrow]=bv.z; Bs[lseg*4+3][lrow]=bv.w;
        __syncthreads();
#pragma unroll
        for (int k = 0; k < BK; k++) {
            float a[4], b[4];
            *(float4*)a = *(float4*)&As[k][ty*4];
            *(float4*)b = *(float4*)&Bs[k][tx*4];
#pragma unroll
            for (int i = 0; i < 4; i++)
#pragma unroll
                for (int j = 0; j < 4; j++)
                    acc[i][j] += a[i]*b[j];
        }
    }
    int n = n0 >> 6;
#pragma unroll
    for (int i = 0; i < 4; i++) {
        int gm = m0 + ty*4 + i;
        if (gm >= MROWS) continue;
        int b = gm / NFQ, f = gm % NFQ;
        __align__(8) __nv_bfloat16 h4[4];
        __align__(8) __nv_bfloat16 l4[4];
#pragma unroll
        for (int j = 0; j < 4; j++) {
            int e = n0 + tx*4 + j;
            float x = (acc[i][j] + qb[e]) * NORMF;
            split_bf16(x, h4[j], l4[j]);
        }
        uint32_t tl = (uint32_t)((b*NHEADS + n)*3 + (f >> 7));
        uint32_t off = tl*TILE_B + sw128((uint32_t)((f & 127)*128 + tx*8));
        *(uint2*)((char*)g_qhtT_hi + off) = *(uint2*)h4;
        *(uint2*)((char*)g_qhtT_lo + off) = *(uint2*)l4;
    }
}

// ============================================================
// FUSED kproj + scores.  grid (50 ptile, 4 etile, 4 b), 256 thr
// Phase 1: kp tile via 24-chunk HMMA mainloop (bulk-DMA 3-stage)
// Phase 2: acc -> bf16 hi/lo B-tiles in smem (bias fused)
// Phase 3: per (head, ftile): S = qht x B, mask/exp/store/stats
// ============================================================
__global__ void __launch_bounds__(256, 2) fused_mma_kernel(const float* __restrict__ kb,
                                                           const int* __restrict__ mask,
                                                           float* __restrict__ out) {
    extern __shared__ char smem[];
    uint32_t sb = smem_u32(smem);
    int t = threadIdx.x, lane = t & 31, w = t >> 5, wm = w >> 2, wn = w & 3;
    int b = blockIdx.z;
    int e0 = blockIdx.y * 128;
    int p0 = blockIdx.x * 128;

    float* kbs = (float*)(smem + KB_OFF);
    int* mS = (int*)(smem + MK_OFF);
    if (t < 128) {
        kbs[t] = kb[e0 + t];
        mS[t] = mask[(size_t)b*NPIX + p0 + t];
    }

    const char* Ap[3] = {
        (const char*)g_kwT_hi + (size_t)blockIdx.y*8*TILE_B,
        (const char*)g_kwT_lo + (size_t)blockIdx.y*8*TILE_B,
        (const char*)g_kwT_hi + (size_t)blockIdx.y*8*TILE_B };
    const char* Bp[3] = {
        (const char*)g_ktT_hi + (size_t)(b*50 + blockIdx.x)*8*TILE_B,
        (const char*)g_ktT_hi + (size_t)(b*50 + blockIdx.x)*8*TILE_B,
        (const char*)g_ktT_lo + (size_t)(b*50 + blockIdx.x)*8*TILE_B };

    if (t == 0) {
#pragma unroll
        for (int i = 0; i < 5; i++) MBINIT(sb + MB_OFF + i*8, 1);
    }
    __syncthreads();

    // ---------------- phase 1: kproj mainloop ----------------
    const int ITERS = 24;
    if (t == 0) {
#pragma unroll
        for (int it = 0; it < 2; it++) {
            int pss = it >> 3, kc = it & 7, st = it % 3;
            MBEXPECT(sb + MB_OFF + st*8, 32768u);
            bulk_cp(sb + STG(st),          Ap[pss] + (size_t)kc*TILE_B, TILE_B, sb + MB_OFF + st*8);
            bulk_cp(sb + STG(st) + 16384u, Bp[pss] + (size_t)kc*TILE_B, TILE_B, sb + MB_OFF + st*8);
        }
    }
    float acc[4][4][4] = {};
    for (int it = 0; it < ITERS; it++) {
        int st = it % 3;
        MBAR_WAIT(sb + MB_OFF + st*8, (uint32_t)((it/3) & 1));
        __syncthreads();
        if (t == 0 && it + 2 < ITERS) {
            int it2 = it + 2;
            int pss = it2 >> 3, kc = it2 & 7, s2 = it2 % 3;
            MBEXPECT(sb + MB_OFF + s2*8, 32768u);
            bulk_cp(sb + STG(s2),          Ap[pss] + (size_t)kc*TILE_B, TILE_B, sb + MB_OFF + s2*8);
            bulk_cp(sb + STG(s2) + 16384u, Bp[pss] + (size_t)kc*TILE_B, TILE_B, sb + MB_OFF + s2*8);
        }
        compute_chunk(sb + STG(st), sb + STG(st) + 16384u, wm, wn, lane, acc);
    }

    // ---------------- phase 2: build B tiles (bf16 hi/lo, bias fused) ----------------
    // Safe without a sync: stages 0/1 (0..64K) had all reads complete before iter 23's
    // barrier; only stage 2 (64..96K) is read by the final chunk, and we don't touch it.
#pragma unroll
    for (int mf = 0; mf < 4; mf++) {
#pragma unroll
        for (int half = 0; half < 2; half++) {
            int e = wm*64 + mf*16 + (lane >> 2) + half*8;
            float bias = kbs[e];
            uint32_t bbase = (uint32_t)(e >> 6) * 32768u;
            int c = e & 63;
#pragma unroll
            for (int nf = 0; nf < 4; nf++) {
#pragma unroll
                for (int j = 0; j < 2; j++) {
                    int p = wn*32 + nf*8 + (lane & 3)*2 + j;
                    float v = acc[mf][nf][half*2 + j] + bias;
                    __nv_bfloat16 hh, ll; split_bf16(v, hh, ll);
                    uint32_t so = sw128((uint32_t)(p*128 + c*2));
                    *(__nv_bfloat16*)(smem + bbase + so) = hh;
                    *(__nv_bfloat16*)(smem + bbase + 16384u + so) = ll;
                }
            }
        }
    }
    __syncthreads();   // B tiles complete; stage-2 reads complete -> A bufs usable

    // ---------------- phase 3: scores per (head, ftile) ----------------
    if (t == 0) {
        const char* ah = (const char*)g_qhtT_hi + (size_t)((b*NHEADS + blockIdx.y*2)*3 + 0)*TILE_B;
        const char* al = (const char*)g_qhtT_lo + (size_t)((b*NHEADS + blockIdx.y*2)*3 + 0)*TILE_B;
        MBEXPECT(sb + MB_OFF + 24, 16384u);
        bulk_cp(sb + A0_OFF, ah, 16384u, sb + MB_OFF + 24);
        MBEXPECT(sb + MB_OFF + 32, 16384u);
        bulk_cp(sb + A1_OFF, al, 16384u, sb + MB_OFF + 32);
    }

    float* rm = (float*)(smem + RM_OFF);
    float* rs = (float*)(smem + RS_OFF);
    size_t obase = (size_t)b*OROWS*NPIX;

    for (int it2 = 0; it2 < 6; it2++) {
        int h = it2 / 3, f = it2 - h*3;
        int n = blockIdx.y*2 + h;
        int m0 = f * 128;
        uint32_t bbase = (uint32_t)h * 32768u;

        float sacc[4][4][4] = {};
        MBAR_WAIT(sb + MB_OFF + 24, (uint32_t)(it2 & 1));
        compute_chunk(sb + A0_OFF, sb + bbase,           wm, wn, lane, sacc);   // Ah*Bh
        compute_chunk(sb + A0_OFF, sb + bbase + 16384u,  wm, wn, lane, sacc);   // Ah*Bl
        __syncthreads();
        if (t == 0 && it2 + 1 < 6) {
            int h2 = (it2+1) / 3, f2 = (it2+1) % 3;
            const char* ah = (const char*)g_qhtT_hi
                + (size_t)((b*NHEADS + blockIdx.y*2 + h2)*3 + f2)*TILE_B;
            MBEXPECT(sb + MB_OFF + 24, 16384u);
            bulk_cp(sb + A0_OFF, ah, 16384u, sb + MB_OFF + 24);
        }
        MBAR_WAIT(sb + MB_OFF + 32, (uint32_t)(it2 & 1));
        compute_chunk(sb + A1_OFF, sb + bbase,           wm, wn, lane, sacc);   // Al*Bh
        __syncthreads();
        if (t == 0 && it2 + 1 < 6) {
            int h2 = (it2+1) / 3, f2 = (it2+1) % 3;
            const char* al = (const char*)g_qhtT_lo
                + (size_t)((b*NHEADS + blockIdx.y*2 + h2)*3 + f2)*TILE_B;
            MBEXPECT(sb + MB_OFF + 32, 16384u);
            bulk_cp(sb + A1_OFF, al, 16384u, sb + MB_OFF + 32);
        }

        // ---- epilogue: max, then exp/store/sum, block stats ----
        float tmax = -INFINITY;
#pragma unroll
        for (int mf = 0; mf < 4; mf++) {
            int fl = wm*64 + mf*16 + (lane >> 2);
#pragma unroll
            for (int half = 0; half < 2; half++) {
                int fg = m0 + fl + half*8;
                if (fg < NFQ) {
#pragma unroll
                    for (int nf = 0; nf < 4; nf++) {
                        int nc = wn*32 + nf*8 + (lane & 3)*2;
                        if (!mS[nc])   tmax = fmaxf(tmax, sacc[mf][nf][half*2]);
                        if (!mS[nc+1]) tmax = fmaxf(tmax, sacc[mf][nf][half*2+1]);
                    }
                }
            }
        }
        rm[t] = tmax;
        __syncthreads();
        for (int s = 128; s > 0; s >>= 1) {
            if (t < s) rm[t] = fmaxf(rm[t], rm[t+s]);
            __syncthreads();
        }
        float bmax = rm[0];
        float base = (bmax > -1e37f) ? bmax : 0.f;

        float tsum = 0.f;
#pragma unroll
        for (int mf = 0; mf < 4; mf++) {
            int fl = wm*64 + mf*16 + (lane >> 2);
#pragma unroll
            for (int half = 0; half < 2; half++) {
                int fg = m0 + fl + half*8;
                if (fg < NFQ) {
                    size_t rowb = obase + ((size_t)fg*NHEADS + n)*NPIX + p0;
#pragma unroll
                    for (int nf = 0; nf < 4; nf++) {
                        int nc = wn*32 + nf*8 + (lane & 3)*2;
                        float ev0 = mS[nc]   ? 0.f : __expf(sacc[mf][nf][half*2]   - base);
                        float ev1 = mS[nc+1] ? 0.f : __expf(sacc[mf][nf][half*2+1] - base);
                        *(float2*)(out + rowb + nc) = make_float2(ev0, ev1);
                        tsum += ev0 + ev1;
                    }
                }
            }
        }
        rs[t] = tsum;
        __syncthreads();
        for (int s = 128; s > 0; s >>= 1) {
            if (t < s) rs[t] += rs[t+s];
            __syncthreads();
        }
        if (t == 0) {
            int pidx = ((b*NHEADS + n)*3 + f)*50 + (int)blockIdx.x;
            g_pmax[pidx] = bmax;
            g_psum[pidx] = rs[0];
        }
        __syncthreads();
    }
}

// ============================================================
// combine: per-batch (M, Z) then per-block scale = exp(bmax-M)/Z
// ============================================================
__global__ void combine_kernel() {
    __shared__ float rm[256];
    __shared__ float rs[256];
    __shared__ float sM, sIZ;
    int b = blockIdx.x, t = threadIdx.x;
    float mv[5], sv[5];
    int cnt = 0;
#pragma unroll
    for (int j = 0; j < 5; j++) {
        int i = t + j*256;
        if (i < CBLK_PER_BATCH) {
            mv[j] = g_pmax[b*CBLK_PER_BATCH + i];
            sv[j] = g_psum[b*CBLK_PER_BATCH + i];
            cnt = j + 1;
        }
    }
    float m = -INFINITY;
    for (int j = 0; j < cnt; j++) m = fmaxf(m, mv[j]);
    float s = 0.f;
    for (int j = 0; j < cnt; j++)
        if (mv[j] > -1e37f) s += sv[j] * __expf(mv[j] - m);
    rm[t] = m; rs[t] = s;
    __syncthreads();
    for (int st = 128; st > 0; st >>= 1) {
        if (t < st) {
            float m1 = rm[t], s1v = rs[t];
            float m2 = rm[t+st], s2v = rs[t+st];
            float M = fmaxf(m1, m2);
            float sum = 0.f;
            if (m1 > -1e37f) sum += s1v * __expf(m1 - M);
            if (m2 > -1e37f) sum += s2v * __expf(m2 - M);
            rm[t] = M; rs[t] = sum;
        }
        __syncthreads();
    }
    if (t == 0) { sM = rm[0]; sIZ = 1.0f / rs[0]; }
    __syncthreads();
    float M = sM, iz = sIZ;
#pragma unroll
    for (int j = 0; j < 5; j++) {
        int i = t + j*256;
        if (i < CBLK_PER_BATCH) {
            float pm = mv[j];
            g_bscale[b*CBLK_PER_BATCH + i] = (pm > -1e37f) ? __expf(pm - M) * iz : 0.f;
        }
    }
}

// ============================================================
// normalize in place: pure per-block scale multiply
// ============================================================
__global__ void norm_kernel(float* __restrict__ out) {
    const int VPB4 = (OROWS*NPIX) / 4;
    const int NP4  = NPIX / 4;
    const int NV   = NBATCH * VPB4;
    float4* o = (float4*)out;
    for (int i = blockIdx.x*blockDim.x + threadIdx.x; i < NV;
         i += gridDim.x*blockDim.x) {
        int b   = i / VPB4;
        int rem = i - b*VPB4;
        int r   = rem / NP4;
        int p4  = rem - r*NP4;
        int pidx = ((b*NHEADS + (r & 7))*3 + (r >> 10))*50 + (p4 >> 5);
        float s = g_bscale[pidx];
        float4 v = o[i];
        v.x *= s; v.y *= s; v.z *= s; v.w *= s;
        o[i] = v;
    }
}

// ============================================================
extern "C" void kernel_launch(void* const* d_in, const int* in_sizes, int n_in,
                              void* d_out, int out_size) {
    const float* q    = (const float*)d_in[0];
    const float* k    = (const float*)d_in[1];
    const int*   mask = (const int*)  d_in[2];
    const float* qw   = (const float*)d_in[3];
    const float* qb   = (const float*)d_in[4];
    const float* kw   = (const float*)d_in[5];
    const float* kb   = (const float*)d_in[6];
    float* out = (float*)d_out;

    cudaFuncSetAttribute(fused_mma_kernel, cudaFuncAttributeMaxDynamicSharedMemorySize, SMEM_SZ);

    kwconv_kernel <<<128, 256>>>(kw);
    kconv_kernel  <<<dim3(200, 8, 4), dim3(32, 8)>>>(k);
    qproj_kernel  <<<dim3(8, 19), 256>>>(q, qw, qb);
    fused_mma_kernel <<<dim3(50, 4, 4), 256, SMEM_SZ>>>(kb, mask, out);
    combine_kernel<<<4, 256>>>();
    norm_kernel   <<<2048, 256>>>(out);
}

// round 16
// speedup vs baseline: 1.1053x; 1.1053x over previous
#include <cuda_runtime.h>
#include <cuda_bf16.h>
#include <stdint.h>
#include <math.h>

#define NBATCH 4
#define NFQ    300
#define QDIM   512
#define HIDDEN 512
#define NHEADS 8
#define HD     64
#define NPIX   6400
#define NORMF  0.125f
#define MROWS  (NBATCH*NFQ)
#define OROWS  (NFQ*NHEADS)          // 2400
#define CBLK_PER_BATCH 1200          // 8 heads * 3 mtiles * 50 ntiles
#define TILE_B 16384
#define TILE_E 8192

// ---------------- static device scratch (pre-swizzled tile layouts) ----------------
__device__ __align__(128) __nv_bfloat16 g_kwT_hi[4*8*TILE_E];
__device__ __align__(128) __nv_bfloat16 g_kwT_lo[4*8*TILE_E];
__device__ __align__(128) __nv_bfloat16 g_ktT_hi[(size_t)4*50*8*TILE_E];
__device__ __align__(128) __nv_bfloat16 g_ktT_lo[(size_t)4*50*8*TILE_E];
__device__ __align__(128) __nv_bfloat16 g_qhtT_hi[4*8*3*TILE_E];
__device__ __align__(128) __nv_bfloat16 g_qhtT_lo[4*8*3*TILE_E];
__device__ __align__(128) __nv_bfloat16 g_kptT_hi[(size_t)4*8*50*TILE_E];
__device__ __align__(128) __nv_bfloat16 g_kptT_lo[(size_t)4*8*50*TILE_E];
__device__ float g_pmax[NBATCH*CBLK_PER_BATCH];
__device__ float g_psum[NBATCH*CBLK_PER_BATCH];
__device__ float g_bscale[NBATCH*CBLK_PER_BATCH];

// ---------------- smem layout ----------------
#define STAGE_SZ 32768u
#define STG(s)   ((uint32_t)(s) * STAGE_SZ)
#define C_OFF  0u
#define KB_OFF 98304u
#define RM_OFF 98304u                   // 8 warp partials + bcast
#define RS_OFF 98368u
#define MK_OFF 100352u
#define MB_OFF 100864u                  // 3 mbarriers x 8B
#define SMEM_SZ 100896u
// scores buffers (within the same 96KB region): Ah|Bh at 0/16K, Al|Bl at 32K/48K
#define SA_H 0u
#define SB_H 16384u
#define SA_L 32768u
#define SB_L 49152u

// ---------------- ptx helpers ----------------
__device__ __forceinline__ uint32_t smem_u32(const void* p) {
    uint32_t a;
    asm("{ .reg .u64 t; cvta.to.shared.u64 t, %1; cvt.u32.u64 %0, t; }" : "=r"(a) : "l"(p));
    return a;
}
__device__ __forceinline__ void bulk_cp(uint32_t dst, const void* src, uint32_t bytes,
                                        uint32_t mbar) {
    asm volatile("cp.async.bulk.shared::cta.global.mbarrier::complete_tx::bytes "
                 "[%0], [%1], %2, [%3];"
                 :: "r"(dst), "l"(src), "r"(bytes), "r"(mbar) : "memory");
}
#define MBINIT(a,c) asm volatile("mbarrier.init.shared.b64 [%0], %1;" :: "r"(a), "r"(c) : "memory")
#define MBEXPECT(a,tx) asm volatile("mbarrier.arrive.expect_tx.shared.b64 _, [%0], %1;" :: "r"(a), "r"(tx) : "memory")
#define MBAR_WAIT(mbar, parity) do { \
    uint32_t _m = (mbar); uint32_t _p = (parity); uint32_t _done; \
    asm volatile("{\n\t.reg .pred p;\n\t" \
        "mbarrier.try_wait.parity.acquire.cta.shared::cta.b64 p, [%1], %2;\n\t" \
        "selp.b32 %0, 1, 0, p;\n\t}" : "=r"(_done) : "r"(_m), "r"(_p) : "memory"); \
    if (!_done) { \
        asm volatile("{\n\t.reg .pred P1;\n\t" \
            "WL_%=:\n\t" \
            "mbarrier.try_wait.parity.acquire.cta.shared::cta.b64 P1, [%0], %1, 0x989680;\n\t" \
            "@P1 bra.uni WD_%=;\n\t" \
            "bra.uni WL_%=;\n\t" \
            "WD_%=:\n\t}" :: "r"(_m), "r"(_p) : "memory"); \
    } \
} while(0)

__device__ __forceinline__ void ldm_x4(uint32_t& r0, uint32_t& r1, uint32_t& r2, uint32_t& r3,
                                       uint32_t addr) {
    asm volatile("ldmatrix.sync.aligned.m8n8.x4.shared.b16 {%0,%1,%2,%3}, [%4];"
                 : "=r"(r0), "=r"(r1), "=r"(r2), "=r"(r3) : "r"(addr));
}
__device__ __forceinline__ void mma_bf16(float* c, uint32_t a0, uint32_t a1, uint32_t a2,
                                         uint32_t a3, uint32_t b0, uint32_t b1) {
    asm volatile("mma.sync.aligned.m16n8k16.row.col.f32.bf16.bf16.f32 "
        "{%0,%1,%2,%3}, {%4,%5,%6,%7}, {%8,%9}, {%0,%1,%2,%3};"
        : "+f"(c[0]), "+f"(c[1]), "+f"(c[2]), "+f"(c[3])
        : "r"(a0), "r"(a1), "r"(a2), "r"(a3), "r"(b0), "r"(b1));
}
__device__ __forceinline__ uint32_t sw128(uint32_t off) { return off ^ ((off >> 3) & 0x70); }

__device__ __forceinline__ void split_bf16(float x, __nv_bfloat16& h, __nv_bfloat16& l) {
    h = __float2bfloat16(x);
    l = __float2bfloat16(x - __bfloat162float(h));
}

// ---- one 64-wide K chunk of 128x128 HMMA (warp tile 64x32, 8 warps) ----
__device__ __forceinline__ void compute_chunk(uint32_t aBase, uint32_t bBase,
                                              int wm, int wn, int lane,
                                              float acc[4][4][4]) {
#pragma unroll
    for (int kk = 0; kk < 64; kk += 16) {
        uint32_t a[4][4];
#pragma unroll
        for (int mf = 0; mf < 4; mf++) {
            int row  = wm*64 + mf*16 + (lane & 15);
            int kcol = kk + ((lane >> 4) << 3);
            uint32_t off = sw128((uint32_t)(row*128 + kcol*2));
            ldm_x4(a[mf][0], a[mf][1], a[mf][2], a[mf][3], aBase + off);
        }
        uint32_t b[4][2];
#pragma unroll
        for (int g = 0; g < 2; g++) {
            int nrow = wn*32 + g*16 + ((lane >> 4) << 3) + (lane & 7);
            int kcol = kk + (((lane >> 3) & 1) << 3);
            uint32_t off = sw128((uint32_t)(nrow*128 + kcol*2));
            uint32_t r0, r1, r2, r3;
            ldm_x4(r0, r1, r2, r3, bBase + off);
            b[g*2][0] = r0; b[g*2][1] = r1; b[g*2+1][0] = r2; b[g*2+1][1] = r3;
        }
#pragma unroll
        for (int mf = 0; mf < 4; mf++)
#pragma unroll
            for (int nf = 0; nf < 4; nf++)
                mma_bf16(acc[mf][nf], a[mf][0], a[mf][1], a[mf][2], a[mf][3],
                         b[nf][0], b[nf][1]);
    }
}

// ============================================================
// convert kw -> pre-swizzled tiles
// ============================================================
__global__ void kwconv_kernel(const float* __restrict__ kw) {
    int n8 = HIDDEN*QDIM/8;
    for (int i = blockIdx.x*blockDim.x + threadIdx.x; i < n8; i += gridDim.x*blockDim.x) {
        int e = i >> 6, dg = i & 63;
        int d0 = dg * 8;
        __align__(16) __nv_bfloat16 h8[8];
        __align__(16) __nv_bfloat16 l8[8];
#pragma unroll
        for (int j = 0; j < 8; j++)
            split_bf16(kw[(size_t)e*QDIM + d0 + j], h8[j], l8[j]);
        uint32_t tile = (uint32_t)(e >> 7)*8 + (d0 >> 6);
        uint32_t off = tile*TILE_B + sw128((uint32_t)((e & 127)*128 + (d0 & 63)*2));
        *(uint4*)((char*)g_kwT_hi + off) = *(uint4*)h8;
        *(uint4*)((char*)g_kwT_lo + off) = *(uint4*)l8;
    }
}

// ============================================================
// convert + transpose k -> pre-swizzled kt tiles
// ============================================================
__global__ void kconv_kernel(const float* __restrict__ kin) {
    __shared__ float tile[64][33];
    int b = blockIdx.z;
    int p0 = blockIdx.x*32, d0 = blockIdx.y*64;
    int tx = threadIdx.x, ty = threadIdx.y;
    const float* src = kin + ((size_t)b*QDIM + d0)*NPIX + p0;
#pragma unroll
    for (int i = 0; i < 8; i++)
        tile[ty + i*8][tx] = src[(size_t)(ty + i*8)*NPIX + tx];
    __syncthreads();
    int tid = ty*32 + tx;
    int pl = tid >> 3, dg = tid & 7;
    __align__(16) __nv_bfloat16 h8[8];
    __align__(16) __nv_bfloat16 l8[8];
#pragma unroll
    for (int j = 0; j < 8; j++)
        split_bf16(tile[dg*8 + j][pl], h8[j], l8[j]);
    int p = p0 + pl;
    uint32_t tl = (uint32_t)((b*50 + (p >> 7))*8 + (d0 >> 6));
    uint32_t off = tl*TILE_B + sw128((uint32_t)((p & 127)*128 + dg*16));
    *(uint4*)((char*)g_ktT_hi + off) = *(uint4*)h8;
    *(uint4*)((char*)g_ktT_lo + off) = *(uint4*)l8;
}

// ============================================================
// q projection (SIMT) -> pre-swizzled qht tiles
// ============================================================
__global__ void qproj_kernel(const float* __restrict__ q,
                             const float* __restrict__ qw,
                             const float* __restrict__ qb) {
    const int BM = 64, BN = 64, BK = 16;
    __shared__ float As[BK][BM];
    __shared__ float Bs[BK][BN];
    int t  = threadIdx.x;
    int tx = t & 15, ty = t >> 4;
    int m0 = blockIdx.y * BM;
    int n0 = blockIdx.x * BN;
    int lrow = t >> 2, lseg = t & 3;

    float acc[4][4] = {};
    for (int k0 = 0; k0 < QDIM; k0 += BK) {
        float4 av = make_float4(0.f, 0.f, 0.f, 0.f);
        int gm = m0 + lrow;
        if (gm < MROWS)
            av = *(const float4*)(q + (size_t)gm*QDIM + k0 + lseg*4);
        float4 bv = *(const float4*)(qw + (size_t)(n0 + lrow)*QDIM + k0 + lseg*4);
        __syncthreads();
        As[lseg*4+0][lrow]=av.x; As[lseg*4+1][lrow]=av.y;
        As[lseg*4+2][lrow]=av.z; As[lseg*4+3][lrow]=av.w;
        Bs[lseg*4+0][lrow]=bv.x; Bs[lseg*4+1][lrow]=bv.y;
        Bs[lseg*4+2][lrow]=bv.z; Bs[lseg*4+3][lrow]=bv.w;
        __syncthreads();
#pragma unroll
        for (int k = 0; k < BK; k++) {
            float a[4], b[4];
            *(float4*)a = *(float4*)&As[k][ty*4];
            *(float4*)b = *(float4*)&Bs[k][tx*4];
#pragma unroll
            for (int i = 0; i < 4; i++)
#pragma unroll
                for (int j = 0; j < 4; j++)
                    acc[i][j] += a[i]*b[j];
        }
    }
    int n = n0 >> 6;
#pragma unroll
    for (int i = 0; i < 4; i++) {
        int gm = m0 + ty*4 + i;
        if (gm >= MROWS) continue;
        int b = gm / NFQ, f = gm % NFQ;
        __align__(8) __nv_bfloat16 h4[4];
        __align__(8) __nv_bfloat16 l4[4];
#pragma unroll
        for (int j = 0; j < 4; j++) {
            int e = n0 + tx*4 + j;
            float x = (acc[i][j] + qb[e]) * NORMF;
            split_bf16(x, h4[j], l4[j]);
        }
        uint32_t tl = (uint32_t)((b*NHEADS + n)*3 + (f >> 7));
        uint32_t off = tl*TILE_B + sw128((uint32_t)((f & 127)*128 + tx*8));
        *(uint2*)((char*)g_qhtT_hi + off) = *(uint2*)h4;
        *(uint2*)((char*)g_qhtT_lo + off) = *(uint2*)l4;
    }
}

// ============================================================
// kproj HMMA: bulk-DMA 3-stage.  grid (50 p, 4 e, 4 b), 256 thr  (R14 exact)
// ============================================================
__global__ void __launch_bounds__(256, 2) kproj_mma_kernel(const float* __restrict__ kb) {
    extern __shared__ char smem[];
    uint32_t sb = smem_u32(smem);
    int t = threadIdx.x, lane = t & 31, w = t >> 5, wm = w >> 2, wn = w & 3;
    int b = blockIdx.z;
    int e0 = blockIdx.y * 128;

    const char* Ap[3] = {
        (const char*)g_kwT_hi + (size_t)blockIdx.y*8*TILE_B,
        (const char*)g_kwT_lo + (size_t)blockIdx.y*8*TILE_B,
        (const char*)g_kwT_hi + (size_t)blockIdx.y*8*TILE_B };
    const char* Bp[3] = {
        (const char*)g_ktT_hi + (size_t)(b*50 + blockIdx.x)*8*TILE_B,
        (const char*)g_ktT_hi + (size_t)(b*50 + blockIdx.x)*8*TILE_B,
        (const char*)g_ktT_lo + (size_t)(b*50 + blockIdx.x)*8*TILE_B };

    if (t == 0) {
        MBINIT(sb + MB_OFF + 0, 1);
        MBINIT(sb + MB_OFF + 8, 1);
        MBINIT(sb + MB_OFF + 16, 1);
    }
    __syncthreads();

    const int ITERS = 24;
    if (t == 0) {
#pragma unroll
        for (int it = 0; it < 2; it++) {
            int pss = it >> 3, kc = it & 7, st = it % 3;
            MBEXPECT(sb + MB_OFF + st*8, 32768u);
            bulk_cp(sb + STG(st),          Ap[pss] + (size_t)kc*TILE_B, TILE_B, sb + MB_OFF + st*8);
            bulk_cp(sb + STG(st) + 16384u, Bp[pss] + (size_t)kc*TILE_B, TILE_B, sb + MB_OFF + st*8);
        }
    }

    float acc[4][4][4] = {};
    for (int it = 0; it < ITERS; it++) {
        int st = it % 3;
        MBAR_WAIT(sb + MB_OFF + st*8, (uint32_t)((it/3) & 1));
        __syncthreads();
        if (t == 0 && it + 2 < ITERS) {
            int it2 = it + 2;
            int pss = it2 >> 3, kc = it2 & 7, s2 = it2 % 3;
            MBEXPECT(sb + MB_OFF + s2*8, 32768u);
            bulk_cp(sb + STG(s2),          Ap[pss] + (size_t)kc*TILE_B, TILE_B, sb + MB_OFF + s2*8);
            bulk_cp(sb + STG(s2) + 16384u, Bp[pss] + (size_t)kc*TILE_B, TILE_B, sb + MB_OFF + s2*8);
        }
        compute_chunk(sb + STG(st), sb + STG(st) + 16384u, wm, wn, lane, acc);
    }
    __syncthreads();   // protect C overlay

    float* Cs = (float*)(smem + C_OFF);
    float* kbs = (float*)(smem + KB_OFF);
    if (t < 128) kbs[t] = kb[e0 + t];
    __syncthreads();
#pragma unroll
    for (int mf = 0; mf < 4; mf++) {
        int e = wm*64 + mf*16 + (lane >> 2);
        float b0 = kbs[e], b1 = kbs[e + 8];
#pragma unroll
        for (int nf = 0; nf < 4; nf++) {
            int p = wn*32 + nf*8 + (lane & 3)*2;
            Cs[e*132 + p]       = acc[mf][nf][0] + b0;
            Cs[e*132 + p + 1]   = acc[mf][nf][1] + b0;
            Cs[(e+8)*132 + p]   = acc[mf][nf][2] + b1;
            Cs[(e+8)*132 + p+1] = acc[mf][nf][3] + b1;
        }
    }
    __syncthreads();
    {
        int pl = t & 127, hd = t >> 7;
        int head = blockIdx.y*2 + hd;
        uint32_t tl = (uint32_t)((b*NHEADS + head)*50 + blockIdx.x);
#pragma unroll
        for (int c8 = 0; c8 < 8; c8++) {
            __align__(16) __nv_bfloat16 h8[8];
            __align__(16) __nv_bfloat16 l8[8];
#pragma unroll
            for (int j = 0; j < 8; j++) {
                float x = Cs[(hd*64 + c8*8 + j)*132 + pl];
                split_bf16(x, h8[j], l8[j]);
            }
            uint32_t off = tl*TILE_B + sw128((uint32_t)(pl*128 + c8*16));
            *(uint4*)((char*)g_kptT_hi + off) = *(uint4*)h8;
            *(uint4*)((char*)g_kptT_lo + off) = *(uint4*)l8;
        }
    }
}

// ============================================================
// scores HMMA: dedup DMA (4 unique tiles, 2 mbarriers, 0 mainloop syncs)
// + shuffle reductions.  grid (50 p, 3 f, 32 bh), 256 thr
// ============================================================
__global__ void __launch_bounds__(256, 2) scores_mma_kernel(const int* __restrict__ mask,
                                                            float* __restrict__ out) {
    extern __shared__ char smem[];
    uint32_t sb = smem_u32(smem);
    int t = threadIdx.x, lane = t & 31, w = t >> 5, wm = w >> 2, wn = w & 3;
    int bh = blockIdx.z;
    int b = bh >> 3, n = bh & 7;
    int m0 = blockIdx.y * 128;
    int p0 = blockIdx.x * 128;

    int* mS = (int*)(smem + MK_OFF);
    if (t < 128) mS[t] = mask[(size_t)b*NPIX + p0 + t];

    const char* qtile_hi = (const char*)g_qhtT_hi + (size_t)((b*NHEADS + n)*3 + blockIdx.y)*TILE_B;
    const char* qtile_lo = (const char*)g_qhtT_lo + (size_t)((b*NHEADS + n)*3 + blockIdx.y)*TILE_B;
    const char* ktile_hi = (const char*)g_kptT_hi + (size_t)((b*NHEADS + n)*50 + blockIdx.x)*TILE_B;
    const char* ktile_lo = (const char*)g_kptT_lo + (size_t)((b*NHEADS + n)*50 + blockIdx.x)*TILE_B;

    if (t == 0) {
        MBINIT(sb + MB_OFF + 0, 1);
        MBINIT(sb + MB_OFF + 8, 1);
    }
    __syncthreads();
    if (t == 0) {
        MBEXPECT(sb + MB_OFF + 0, 32768u);
        bulk_cp(sb + SA_H, qtile_hi, TILE_B, sb + MB_OFF + 0);
        bulk_cp(sb + SB_H, ktile_hi, TILE_B, sb + MB_OFF + 0);
        MBEXPECT(sb + MB_OFF + 8, 32768u);
        bulk_cp(sb + SA_L, qtile_lo, TILE_B, sb + MB_OFF + 8);
        bulk_cp(sb + SB_L, ktile_lo, TILE_B, sb + MB_OFF + 8);
    }

    float acc[4][4][4] = {};
    MBAR_WAIT(sb + MB_OFF + 0, 0u);
    compute_chunk(sb + SA_H, sb + SB_H, wm, wn, lane, acc);   // Ah*Bh
    MBAR_WAIT(sb + MB_OFF + 8, 0u);
    compute_chunk(sb + SA_H, sb + SB_L, wm, wn, lane, acc);   // Ah*Bl
    compute_chunk(sb + SA_L, sb + SB_H, wm, wn, lane, acc);   // Al*Bh

    // ---- epilogue pass 1: per-thread max, warp-shuffle reduce ----
    float* rm = (float*)(smem + RM_OFF);
    float* rs = (float*)(smem + RS_OFF);
    float tmax = -INFINITY;
#pragma unroll
    for (int mf = 0; mf < 4; mf++) {
        int fl = wm*64 + mf*16 + (lane >> 2);
#pragma unroll
        for (int half = 0; half < 2; half++) {
            int fg = m0 + fl + half*8;
            if (fg < NFQ) {
#pragma unroll
                for (int nf = 0; nf < 4; nf++) {
                    int nc = wn*32 + nf*8 + (lane & 3)*2;
                    if (!mS[nc])   tmax = fmaxf(tmax, acc[mf][nf][half*2]);
                    if (!mS[nc+1]) tmax = fmaxf(tmax, acc[mf][nf][half*2+1]);
                }
            }
        }
    }
#pragma unroll
    for (int o = 16; o > 0; o >>= 1)
        tmax = fmaxf(tmax, __shfl_xor_sync(0xFFFFFFFFu, tmax, o));
    if (lane == 0) rm[w] = tmax;
    __syncthreads();
    if (t == 0) {
        float m = rm[0];
#pragma unroll
        for (int i = 1; i < 8; i++) m = fmaxf(m, rm[i]);
        rm[0] = m;
    }
    __syncthreads();
    float bmax = rm[0];
    float base = (bmax > -1e37f) ? bmax : 0.f;

    // ---- pass 2: exp, store, sum (shuffle reduce) ----
    size_t obase = (size_t)b*OROWS*NPIX;
    float tsum = 0.f;
#pragma unroll
    for (int mf = 0; mf < 4; mf++) {
        int fl = wm*64 + mf*16 + (lane >> 2);
#pragma unroll
        for (int half = 0; half < 2; half++) {
            int fg = m0 + fl + half*8;
            if (fg < NFQ) {
                size_t rowb = obase + ((size_t)fg*NHEADS + n)*NPIX + p0;
#pragma unroll
                for (int nf = 0; nf < 4; nf++) {
                    int nc = wn*32 + nf*8 + (lane & 3)*2;
                    float e0 = mS[nc]   ? 0.f : __expf(acc[mf][nf][half*2]   - base);
                    float e1 = mS[nc+1] ? 0.f : __expf(acc[mf][nf][half*2+1] - base);
                    *(float2*)(out + rowb + nc) = make_float2(e0, e1);
                    tsum += e0 + e1;
                }
            }
        }
    }
#pragma unroll
    for (int o = 16; o > 0; o >>= 1)
        tsum += __shfl_xor_sync(0xFFFFFFFFu, tsum, o);
    if (lane == 0) rs[w] = tsum;
    __syncthreads();
    if (t == 0) {
        float s = rs[0];
#pragma unroll
        for (int i = 1; i < 8; i++) s += rs[i];
        int pidx = (int)blockIdx.z*150 + (int)blockIdx.y*50 + (int)blockIdx.x;
        g_pmax[pidx] = bmax;
        g_psum[pidx] = s;
    }
}

// ============================================================
// combine: per-batch (M, Z) then per-block scale = exp(bmax-M)/Z
// ============================================================
__global__ void combine_kernel() {
    __shared__ float rm[256];
    __shared__ float rs[256];
    __shared__ float sM, sIZ;
    int b = blockIdx.x, t = threadIdx.x;
    float mv[5], sv[5];
    int cnt = 0;
#pragma unroll
    for (int j = 0; j < 5; j++) {
        int i = t + j*256;
        if (i < CBLK_PER_BATCH) {
            mv[j] = g_pmax[b*CBLK_PER_BATCH + i];
            sv[j] = g_psum[b*CBLK_PER_BATCH + i];
            cnt = j + 1;
        }
    }
    float m = -INFINITY;
    for (int j = 0; j < cnt; j++) m = fmaxf(m, mv[j]);
    float s = 0.f;
    for (int j = 0; j < cnt; j++)
        if (mv[j] > -1e37f) s += sv[j] * __expf(mv[j] - m);
    rm[t] = m; rs[t] = s;
    __syncthreads();
    for (int st = 128; st > 0; st >>= 1) {
        if (t < st) {
            float m1 = rm[t], s1v = rs[t];
            float m2 = rm[t+st], s2v = rs[t+st];
            float M = fmaxf(m1, m2);
            float sum = 0.f;
            if (m1 > -1e37f) sum += s1v * __expf(m1 - M);
            if (m2 > -1e37f) sum += s2v * __expf(m2 - M);
            rm[t] = M; rs[t] = sum;
        }
        __syncthreads();
    }
    if (t == 0) { sM = rm[0]; sIZ = 1.0f / rs[0]; }
    __syncthreads();
    float M = sM, iz = sIZ;
#pragma unroll
    for (int j = 0; j < 5; j++) {
        int i = t + j*256;
        if (i < CBLK_PER_BATCH) {
            float pm = mv[j];
            g_bscale[b*CBLK_PER_BATCH + i] = (pm > -1e37f) ? __expf(pm - M) * iz : 0.f;
        }
    }
}

// ============================================================
// normalize in place: pure per-block scale multiply
// ============================================================
__global__ void norm_kernel(float* __restrict__ out) {
    const int VPB4 = (OROWS*NPIX) / 4;
    const int NP4  = NPIX / 4;
    const int NV   = NBATCH * VPB4;
    float4* o = (float4*)out;
    for (int i = blockIdx.x*blockDim.x + threadIdx.x; i < NV;
         i += gridDim.x*blockDim.x) {
        int b   = i / VPB4;
        int rem = i - b*VPB4;
        int r   = rem / NP4;
        int p4  = rem - r*NP4;
        int pidx = ((b*NHEADS + (r & 7))*3 + (r >> 10))*50 + (p4 >> 5);
        float s = g_bscale[pidx];
        float4 v = o[i];
        v.x *= s; v.y *= s; v.z *= s; v.w *= s;
        o[i] = v;
    }
}

// ============================================================
extern "C" void kernel_launch(void* const* d_in, const int* in_sizes, int n_in,
                              void* d_out, int out_size) {
    const float* q    = (const float*)d_in[0];
    const float* k    = (const float*)d_in[1];
    const int*   mask = (const int*)  d_in[2];
    const float* qw   = (const float*)d_in[3];
    const float* qb   = (const float*)d_in[4];
    const float* kw   = (const float*)d_in[5];
    const float* kb   = (const float*)d_in[6];
    float* out = (float*)d_out;

    cudaFuncSetAttribute(kproj_mma_kernel,  cudaFuncAttributeMaxDynamicSharedMemorySize, SMEM_SZ);
    cudaFuncSetAttribute(scores_mma_kernel, cudaFuncAttributeMaxDynamicSharedMemorySize, SMEM_SZ);

    kwconv_kernel <<<128, 256>>>(kw);
    kconv_kernel  <<<dim3(200, 8, 4), dim3(32, 8)>>>(k);
    qproj_kernel  <<<dim3(8, 19), 256>>>(q, qw, qb);
    kproj_mma_kernel <<<dim3(50, 4, 4),  256, SMEM_SZ>>>(kb);
    scores_mma_kernel<<<dim3(50, 3, 32), 256, SMEM_SZ>>>(mask, out);
    combine_kernel<<<4, 256>>>();
    norm_kernel   <<<2048, 256>>>(out);
}

// round 17
// speedup vs baseline: 1.1410x; 1.0323x over previous
#include <cuda_runtime.h>
#include <cuda_bf16.h>
#include <stdint.h>
#include <math.h>

#define NBATCH 4
#define NFQ    300
#define QDIM   512
#define HIDDEN 512
#define NHEADS 8
#define HD     64
#define NPIX   6400
#define NORMF  0.125f
#define MROWS  (NBATCH*NFQ)
#define OROWS  (NFQ*NHEADS)          // 2400
#define CBLK_PER_BATCH 1200          // 8 heads * 3 mtiles * 50 ntiles
#define TILE_B 16384
#define TILE_E 8192

// ---------------- static device scratch (pre-swizzled tile layouts) ----------------
__device__ __align__(128) __nv_bfloat16 g_kwT_hi[4*8*TILE_E];
__device__ __align__(128) __nv_bfloat16 g_kwT_lo[4*8*TILE_E];
__device__ __align__(128) __nv_bfloat16 g_ktT_hi[(size_t)4*50*8*TILE_E];
__device__ __align__(128) __nv_bfloat16 g_ktT_lo[(size_t)4*50*8*TILE_E];
__device__ __align__(128) __nv_bfloat16 g_qhtT_hi[4*8*3*TILE_E];
__device__ __align__(128) __nv_bfloat16 g_qhtT_lo[4*8*3*TILE_E];
__device__ __align__(128) __nv_bfloat16 g_kptT_hi[(size_t)4*8*50*TILE_E];
__device__ __align__(128) __nv_bfloat16 g_kptT_lo[(size_t)4*8*50*TILE_E];
__device__ float g_pmax[NBATCH*CBLK_PER_BATCH];
__device__ float g_psum[NBATCH*CBLK_PER_BATCH];
__device__ float g_bscale[NBATCH*CBLK_PER_BATCH];

// ---------------- smem layout ----------------
#define STAGE_SZ 32768u
#define STG(s)   ((uint32_t)(s) * STAGE_SZ)
#define C_OFF  0u
#define KB_OFF 98304u
#define RM_OFF 98304u                   // 8 warp partials + bcast
#define RS_OFF 98368u
#define MK_OFF 100352u
#define MB_OFF 100864u                  // 3 mbarriers x 8B
#define SMEM_SZ 100896u
// scores buffers: Ah|Bh at 0/16K, Al|Bl at 32K/48K
#define SA_H 0u
#define SB_H 16384u
#define SA_L 32768u
#define SB_L 49152u

// ---------------- ptx helpers ----------------
__device__ __forceinline__ uint32_t smem_u32(const void* p) {
    uint32_t a;
    asm("{ .reg .u64 t; cvta.to.shared.u64 t, %1; cvt.u32.u64 %0, t; }" : "=r"(a) : "l"(p));
    return a;
}
__device__ __forceinline__ void bulk_cp(uint32_t dst, const void* src, uint32_t bytes,
                                        uint32_t mbar) {
    asm volatile("cp.async.bulk.shared::cta.global.mbarrier::complete_tx::bytes "
                 "[%0], [%1], %2, [%3];"
                 :: "r"(dst), "l"(src), "r"(bytes), "r"(mbar) : "memory");
}
#define MBINIT(a,c) asm volatile("mbarrier.init.shared.b64 [%0], %1;" :: "r"(a), "r"(c) : "memory")
#define MBEXPECT(a,tx) asm volatile("mbarrier.arrive.expect_tx.shared.b64 _, [%0], %1;" :: "r"(a), "r"(tx) : "memory")
#define MBAR_WAIT(mbar, parity) do { \
    uint32_t _m = (mbar); uint32_t _p = (parity); uint32_t _done; \
    asm volatile("{\n\t.reg .pred p;\n\t" \
        "mbarrier.try_wait.parity.acquire.cta.shared::cta.b64 p, [%1], %2;\n\t" \
        "selp.b32 %0, 1, 0, p;\n\t}" : "=r"(_done) : "r"(_m), "r"(_p) : "memory"); \
    if (!_done) { \
        asm volatile("{\n\t.reg .pred P1;\n\t" \
            "WL_%=:\n\t" \
            "mbarrier.try_wait.parity.acquire.cta.shared::cta.b64 P1, [%0], %1, 0x989680;\n\t" \
            "@P1 bra.uni WD_%=;\n\t" \
            "bra.uni WL_%=;\n\t" \
            "WD_%=:\n\t}" :: "r"(_m), "r"(_p) : "memory"); \
    } \
} while(0)

__device__ __forceinline__ void ldm_x4(uint32_t& r0, uint32_t& r1, uint32_t& r2, uint32_t& r3,
                                       uint32_t addr) {
    asm volatile("ldmatrix.sync.aligned.m8n8.x4.shared.b16 {%0,%1,%2,%3}, [%4];"
                 : "=r"(r0), "=r"(r1), "=r"(r2), "=r"(r3) : "r"(addr));
}
__device__ __forceinline__ void mma_bf16(float* c, uint32_t a0, uint32_t a1, uint32_t a2,
                                         uint32_t a3, uint32_t b0, uint32_t b1) {
    asm volatile("mma.sync.aligned.m16n8k16.row.col.f32.bf16.bf16.f32 "
        "{%0,%1,%2,%3}, {%4,%5,%6,%7}, {%8,%9}, {%0,%1,%2,%3};"
        : "+f"(c[0]), "+f"(c[1]), "+f"(c[2]), "+f"(c[3])
        : "r"(a0), "r"(a1), "r"(a2), "r"(a3), "r"(b0), "r"(b1));
}
__device__ __forceinline__ uint32_t sw128(uint32_t off) { return off ^ ((off >> 3) & 0x70); }

__device__ __forceinline__ void split_bf16(float x, __nv_bfloat16& h, __nv_bfloat16& l) {
    h = __float2bfloat16(x);
    l = __float2bfloat16(x - __bfloat162float(h));
}

// ---- one 64-wide K chunk of 128x128 HMMA (warp tile 64x32, 8 warps) ----
__device__ __forceinline__ void compute_chunk(uint32_t aBase, uint32_t bBase,
                                              int wm, int wn, int lane,
                                              float acc[4][4][4]) {
#pragma unroll
    for (int kk = 0; kk < 64; kk += 16) {
        uint32_t a[4][4];
#pragma unroll
        for (int mf = 0; mf < 4; mf++) {
            int row  = wm*64 + mf*16 + (lane & 15);
            int kcol = kk + ((lane >> 4) << 3);
            uint32_t off = sw128((uint32_t)(row*128 + kcol*2));
            ldm_x4(a[mf][0], a[mf][1], a[mf][2], a[mf][3], aBase + off);
        }
        uint32_t b[4][2];
#pragma unroll
        for (int g = 0; g < 2; g++) {
            int nrow = wn*32 + g*16 + ((lane >> 4) << 3) + (lane & 7);
            int kcol = kk + (((lane >> 3) & 1) << 3);
            uint32_t off = sw128((uint32_t)(nrow*128 + kcol*2));
            uint32_t r0, r1, r2, r3;
            ldm_x4(r0, r1, r2, r3, bBase + off);
            b[g*2][0] = r0; b[g*2][1] = r1; b[g*2+1][0] = r2; b[g*2+1][1] = r3;
        }
#pragma unroll
        for (int mf = 0; mf < 4; mf++)
#pragma unroll
            for (int nf = 0; nf < 4; nf++)
                mma_bf16(acc[mf][nf], a[mf][0], a[mf][1], a[mf][2], a[mf][3],
                         b[nf][0], b[nf][1]);
    }
}

// ============================================================
// convert kw -> pre-swizzled tiles
// ============================================================
__global__ void kwconv_kernel(const float* __restrict__ kw) {
    int n8 = HIDDEN*QDIM/8;
    for (int i = blockIdx.x*blockDim.x + threadIdx.x; i < n8; i += gridDim.x*blockDim.x) {
        int e = i >> 6, dg = i & 63;
        int d0 = dg * 8;
        __align__(16) __nv_bfloat16 h8[8];
        __align__(16) __nv_bfloat16 l8[8];
#pragma unroll
        for (int j = 0; j < 8; j++)
            split_bf16(kw[(size_t)e*QDIM + d0 + j], h8[j], l8[j]);
        uint32_t tile = (uint32_t)(e >> 7)*8 + (d0 >> 6);
        uint32_t off = tile*TILE_B + sw128((uint32_t)((e & 127)*128 + (d0 & 63)*2));
        *(uint4*)((char*)g_kwT_hi + off) = *(uint4*)h8;
        *(uint4*)((char*)g_kwT_lo + off) = *(uint4*)l8;
    }
}

// ============================================================
// convert + transpose k -> pre-swizzled kt tiles
// ============================================================
__global__ void kconv_kernel(const float* __restrict__ kin) {
    __shared__ float tile[64][33];
    int b = blockIdx.z;
    int p0 = blockIdx.x*32, d0 = blockIdx.y*64;
    int tx = threadIdx.x, ty = threadIdx.y;
    const float* src = kin + ((size_t)b*QDIM + d0)*NPIX + p0;
#pragma unroll
    for (int i = 0; i < 8; i++)
        tile[ty + i*8][tx] = src[(size_t)(ty + i*8)*NPIX + tx];
    __syncthreads();
    int tid = ty*32 + tx;
    int pl = tid >> 3, dg = tid & 7;
    __align__(16) __nv_bfloat16 h8[8];
    __align__(16) __nv_bfloat16 l8[8];
#pragma unroll
    for (int j = 0; j < 8; j++)
        split_bf16(tile[dg*8 + j][pl], h8[j], l8[j]);
    int p = p0 + pl;
    uint32_t tl = (uint32_t)((b*50 + (p >> 7))*8 + (d0 >> 6));
    uint32_t off = tl*TILE_B + sw128((uint32_t)((p & 127)*128 + dg*16));
    *(uint4*)((char*)g_ktT_hi + off) = *(uint4*)h8;
    *(uint4*)((char*)g_ktT_lo + off) = *(uint4*)l8;
}

// ============================================================
// q projection (SIMT) -> pre-swizzled qht tiles
// ============================================================
__global__ void qproj_kernel(const float* __restrict__ q,
                             const float* __restrict__ qw,
                             const float* __restrict__ qb) {
    const int BM = 64, BN = 64, BK = 16;
    __shared__ float As[BK][BM];
    __shared__ float Bs[BK][BN];
    int t  = threadIdx.x;
    int tx = t & 15, ty = t >> 4;
    int m0 = blockIdx.y * BM;
    int n0 = blockIdx.x * BN;
    int lrow = t >> 2, lseg = t & 3;

    float acc[4][4] = {};
    for (int k0 = 0; k0 < QDIM; k0 += BK) {
        float4 av = make_float4(0.f, 0.f, 0.f, 0.f);
        int gm = m0 + lrow;
        if (gm < MROWS)
            av = *(const float4*)(q + (size_t)gm*QDIM + k0 + lseg*4);
        float4 bv = *(const float4*)(qw + (size_t)(n0 + lrow)*QDIM + k0 + lseg*4);
        __syncthreads();
        As[lseg*4+0][lrow]=av.x; As[lseg*4+1][lrow]=av.y;
        As[lseg*4+2][lrow]=av.z; As[lseg*4+3][lrow]=av.w;
        Bs[lseg*4+0][lrow]=bv.x; Bs[lseg*4+1][lrow]=bv.y;
        Bs[lseg*4+2][lrow]=bv.z; Bs[lseg*4+3][lrow]=bv.w;
        __syncthreads();
#pragma unroll
        for (int k = 0; k < BK; k++) {
            float a[4], b[4];
            *(float4*)a = *(float4*)&As[k][ty*4];
            *(float4*)b = *(float4*)&Bs[k][tx*4];
#pragma unroll
            for (int i = 0; i < 4; i++)
#pragma unroll
                for (int j = 0; j < 4; j++)
                    acc[i][j] += a[i]*b[j];
        }
    }
    int n = n0 >> 6;
#pragma unroll
    for (int i = 0; i < 4; i++) {
        int gm = m0 + ty*4 + i;
        if (gm >= MROWS) continue;
        int b = gm / NFQ, f = gm % NFQ;
        __align__(8) __nv_bfloat16 h4[4];
        __align__(8) __nv_bfloat16 l4[4];
#pragma unroll
        for (int j = 0; j < 4; j++) {
            int e = n0 + tx*4 + j;
            float x = (acc[i][j] + qb[e]) * NORMF;
            split_bf16(x, h4[j], l4[j]);
        }
        uint32_t tl = (uint32_t)((b*NHEADS + n)*3 + (f >> 7));
        uint32_t off = tl*TILE_B + sw128((uint32_t)((f & 127)*128 + tx*8));
        *(uint2*)((char*)g_qhtT_hi + off) = *(uint2*)h4;
        *(uint2*)((char*)g_qhtT_lo + off) = *(uint2*)l4;
    }
}

// ============================================================
// kproj HMMA: bulk-DMA 3-stage.  grid (50 p, 4 e, 4 b), 256 thr
// ============================================================
__global__ void __launch_bounds__(256, 2) kproj_mma_kernel(const float* __restrict__ kb) {
    extern __shared__ char smem[];
    uint32_t sb = smem_u32(smem);
    int t = threadIdx.x, lane = t & 31, w = t >> 5, wm = w >> 2, wn = w & 3;
    int b = blockIdx.z;
    int e0 = blockIdx.y * 128;

    const char* Ap[3] = {
        (const char*)g_kwT_hi + (size_t)blockIdx.y*8*TILE_B,
        (const char*)g_kwT_lo + (size_t)blockIdx.y*8*TILE_B,
        (const char*)g_kwT_hi + (size_t)blockIdx.y*8*TILE_B };
    const char* Bp[3] = {
        (const char*)g_ktT_hi + (size_t)(b*50 + blockIdx.x)*8*TILE_B,
        (const char*)g_ktT_hi + (size_t)(b*50 + blockIdx.x)*8*TILE_B,
        (const char*)g_ktT_lo + (size_t)(b*50 + blockIdx.x)*8*TILE_B };

    if (t == 0) {
        MBINIT(sb + MB_OFF + 0, 1);
        MBINIT(sb + MB_OFF + 8, 1);
        MBINIT(sb + MB_OFF + 16, 1);
    }
    __syncthreads();

    const int ITERS = 24;
    if (t == 0) {
#pragma unroll
        for (int it = 0; it < 2; it++) {
            int pss = it >> 3, kc = it & 7, st = it % 3;
            MBEXPECT(sb + MB_OFF + st*8, 32768u);
            bulk_cp(sb + STG(st),          Ap[pss] + (size_t)kc*TILE_B, TILE_B, sb + MB_OFF + st*8);
            bulk_cp(sb + STG(st) + 16384u, Bp[pss] + (size_t)kc*TILE_B, TILE_B, sb + MB_OFF + st*8);
        }
    }

    float acc[4][4][4] = {};
    for (int it = 0; it < ITERS; it++) {
        int st = it % 3;
        MBAR_WAIT(sb + MB_OFF + st*8, (uint32_t)((it/3) & 1));
        __syncthreads();
        if (t == 0 && it + 2 < ITERS) {
            int it2 = it + 2;
            int pss = it2 >> 3, kc = it2 & 7, s2 = it2 % 3;
            MBEXPECT(sb + MB_OFF + s2*8, 32768u);
            bulk_cp(sb + STG(s2),          Ap[pss] + (size_t)kc*TILE_B, TILE_B, sb + MB_OFF + s2*8);
            bulk_cp(sb + STG(s2) + 16384u, Bp[pss] + (size_t)kc*TILE_B, TILE_B, sb + MB_OFF + s2*8);
        }
        compute_chunk(sb + STG(st), sb + STG(st) + 16384u, wm, wn, lane, acc);
    }
    __syncthreads();   // protect C overlay

    float* Cs = (float*)(smem + C_OFF);
    float* kbs = (float*)(smem + KB_OFF);
    if (t < 128) kbs[t] = kb[e0 + t];
    __syncthreads();
#pragma unroll
    for (int mf = 0; mf < 4; mf++) {
        int e = wm*64 + mf*16 + (lane >> 2);
        float b0 = kbs[e], b1 = kbs[e + 8];
#pragma unroll
        for (int nf = 0; nf < 4; nf++) {
            int p = wn*32 + nf*8 + (lane & 3)*2;
            Cs[e*132 + p]       = acc[mf][nf][0] + b0;
            Cs[e*132 + p + 1]   = acc[mf][nf][1] + b0;
            Cs[(e+8)*132 + p]   = acc[mf][nf][2] + b1;
            Cs[(e+8)*132 + p+1] = acc[mf][nf][3] + b1;
        }
    }
    __syncthreads();
    {
        int pl = t & 127, hd = t >> 7;
        int head = blockIdx.y*2 + hd;
        uint32_t tl = (uint32_t)((b*NHEADS + head)*50 + blockIdx.x);
#pragma unroll
        for (int c8 = 0; c8 < 8; c8++) {
            __align__(16) __nv_bfloat16 h8[8];
            __align__(16) __nv_bfloat16 l8[8];
#pragma unroll
            for (int j = 0; j < 8; j++) {
                float x = Cs[(hd*64 + c8*8 + j)*132 + pl];
                split_bf16(x, h8[j], l8[j]);
            }
            uint32_t off = tl*TILE_B + sw128((uint32_t)(pl*128 + c8*16));
            *(uint4*)((char*)g_kptT_hi + off) = *(uint4*)h8;
            *(uint4*)((char*)g_kptT_lo + off) = *(uint4*)l8;
        }
    }
}

// ============================================================
// scores HMMA: dedup DMA + shuffle reductions.  grid (50, 3, 32), 256 thr
// ============================================================
__global__ void __launch_bounds__(256, 2) scores_mma_kernel(const int* __restrict__ mask,
                                                            float* __restrict__ out) {
    extern __shared__ char smem[];
    uint32_t sb = smem_u32(smem);
    int t = threadIdx.x, lane = t & 31, w = t >> 5, wm = w >> 2, wn = w & 3;
    int bh = blockIdx.z;
    int b = bh >> 3, n = bh & 7;
    int m0 = blockIdx.y * 128;
    int p0 = blockIdx.x * 128;

    int* mS = (int*)(smem + MK_OFF);
    if (t < 128) mS[t] = mask[(size_t)b*NPIX + p0 + t];

    const char* qtile_hi = (const char*)g_qhtT_hi + (size_t)((b*NHEADS + n)*3 + blockIdx.y)*TILE_B;
    const char* qtile_lo = (const char*)g_qhtT_lo + (size_t)((b*NHEADS + n)*3 + blockIdx.y)*TILE_B;
    const char* ktile_hi = (const char*)g_kptT_hi + (size_t)((b*NHEADS + n)*50 + blockIdx.x)*TILE_B;
    const char* ktile_lo = (const char*)g_kptT_lo + (size_t)((b*NHEADS + n)*50 + blockIdx.x)*TILE_B;

    if (t == 0) {
        MBINIT(sb + MB_OFF + 0, 1);
        MBINIT(sb + MB_OFF + 8, 1);
    }
    __syncthreads();
    if (t == 0) {
        MBEXPECT(sb + MB_OFF + 0, 32768u);
        bulk_cp(sb + SA_H, qtile_hi, TILE_B, sb + MB_OFF + 0);
        bulk_cp(sb + SB_H, ktile_hi, TILE_B, sb + MB_OFF + 0);
        MBEXPECT(sb + MB_OFF + 8, 32768u);
        bulk_cp(sb + SA_L, qtile_lo, TILE_B, sb + MB_OFF + 8);
        bulk_cp(sb + SB_L, ktile_lo, TILE_B, sb + MB_OFF + 8);
    }

    float acc[4][4][4] = {};
    MBAR_WAIT(sb + MB_OFF + 0, 0u);
    compute_chunk(sb + SA_H, sb + SB_H, wm, wn, lane, acc);   // Ah*Bh
    MBAR_WAIT(sb + MB_OFF + 8, 0u);
    compute_chunk(sb + SA_H, sb + SB_L, wm, wn, lane, acc);   // Ah*Bl
    compute_chunk(sb + SA_L, sb + SB_H, wm, wn, lane, acc);   // Al*Bh

    // ---- epilogue pass 1: per-thread max, warp-shuffle reduce ----
    float* rm = (float*)(smem + RM_OFF);
    float* rs = (float*)(smem + RS_OFF);
    float tmax = -INFINITY;
#pragma unroll
    for (int mf = 0; mf < 4; mf++) {
        int fl = wm*64 + mf*16 + (lane >> 2);
#pragma unroll
        for (int half = 0; half < 2; half++) {
            int fg = m0 + fl + half*8;
            if (fg < NFQ) {
#pragma unroll
                for (int nf = 0; nf < 4; nf++) {
                    int nc = wn*32 + nf*8 + (lane & 3)*2;
                    if (!mS[nc])   tmax = fmaxf(tmax, acc[mf][nf][half*2]);
                    if (!mS[nc+1]) tmax = fmaxf(tmax, acc[mf][nf][half*2+1]);
                }
            }
        }
    }
#pragma unroll
    for (int o = 16; o > 0; o >>= 1)
        tmax = fmaxf(tmax, __shfl_xor_sync(0xFFFFFFFFu, tmax, o));
    if (lane == 0) rm[w] = tmax;
    __syncthreads();
    if (t == 0) {
        float m = rm[0];
#pragma unroll
        for (int i = 1; i < 8; i++) m = fmaxf(m, rm[i]);
        rm[0] = m;
    }
    __syncthreads();
    float bmax = rm[0];
    float base = (bmax > -1e37f) ? bmax : 0.f;

    // ---- pass 2: exp, store, sum (shuffle reduce) ----
    size_t obase = (size_t)b*OROWS*NPIX;
    float tsum = 0.f;
#pragma unroll
    for (int mf = 0; mf < 4; mf++) {
        int fl = wm*64 + mf*16 + (lane >> 2);
#pragma unroll
        for (int half = 0; half < 2; half++) {
            int fg = m0 + fl + half*8;
            if (fg < NFQ) {
                size_t rowb = obase + ((size_t)fg*NHEADS + n)*NPIX + p0;
#pragma unroll
                for (int nf = 0; nf < 4; nf++) {
                    int nc = wn*32 + nf*8 + (lane & 3)*2;
                    float e0 = mS[nc]   ? 0.f : __expf(acc[mf][nf][half*2]   - base);
                    float e1 = mS[nc+1] ? 0.f : __expf(acc[mf][nf][half*2+1] - base);
                    *(float2*)(out + rowb + nc) = make_float2(e0, e1);
                    tsum += e0 + e1;
                }
            }
        }
    }
#pragma unroll
    for (int o = 16; o > 0; o >>= 1)
        tsum += __shfl_xor_sync(0xFFFFFFFFu, tsum, o);
    if (lane == 0) rs[w] = tsum;
    __syncthreads();
    if (t == 0) {
        float s = rs[0];
#pragma unroll
        for (int i = 1; i < 8; i++) s += rs[i];
        int pidx = (int)blockIdx.z*150 + (int)blockIdx.y*50 + (int)blockIdx.x;
        g_pmax[pidx] = bmax;
        g_psum[pidx] = s;
    }
}

// ============================================================
// combine: per-batch (M, Z) then per-block scale = exp(bmax-M)/Z
// ============================================================
__global__ void combine_kernel() {
    __shared__ float rm[256];
    __shared__ float rs[256];
    __shared__ float sM, sIZ;
    int b = blockIdx.x, t = threadIdx.x;
    float mv[5], sv[5];
    int cnt = 0;
#pragma unroll
    for (int j = 0; j < 5; j++) {
        int i = t + j*256;
        if (i < CBLK_PER_BATCH) {
            mv[j] = g_pmax[b*CBLK_PER_BATCH + i];
            sv[j] = g_psum[b*CBLK_PER_BATCH + i];
            cnt = j + 1;
        }
    }
    float m = -INFINITY;
    for (int j = 0; j < cnt; j++) m = fmaxf(m, mv[j]);
    float s = 0.f;
    for (int j = 0; j < cnt; j++)
        if (mv[j] > -1e37f) s += sv[j] * __expf(mv[j] - m);
    rm[t] = m; rs[t] = s;
    __syncthreads();
    for (int st = 128; st > 0; st >>= 1) {
        if (t < st) {
            float m1 = rm[t], s1v = rs[t];
            float m2 = rm[t+st], s2v = rs[t+st];
            float M = fmaxf(m1, m2);
            float sum = 0.f;
            if (m1 > -1e37f) sum += s1v * __expf(m1 - M);
            if (m2 > -1e37f) sum += s2v * __expf(m2 - M);
            rm[t] = M; rs[t] = sum;
        }
        __syncthreads();
    }
    if (t == 0) { sM = rm[0]; sIZ = 1.0f / rs[0]; }
    __syncthreads();
    float M = sM, iz = sIZ;
#pragma unroll
    for (int j = 0; j < 5; j++) {
        int i = t + j*256;
        if (i < CBLK_PER_BATCH) {
            float pm = mv[j];
            g_bscale[b*CBLK_PER_BATCH + i] = (pm > -1e37f) ? __expf(pm - M) * iz : 0.f;
        }
    }
}

// ============================================================
// normalize in place: pure per-block scale multiply
// ============================================================
__global__ void norm_kernel(float* __restrict__ out) {
    const int VPB4 = (OROWS*NPIX) / 4;
    const int NP4  = NPIX / 4;
    const int NV   = NBATCH * VPB4;
    float4* o = (float4*)out;
    for (int i = blockIdx.x*blockDim.x + threadIdx.x; i < NV;
         i += gridDim.x*blockDim.x) {
        int b   = i / VPB4;
        int rem = i - b*VPB4;
        int r   = rem / NP4;
        int p4  = rem - r*NP4;
        int pidx = ((b*NHEADS + (r & 7))*3 + (r >> 10))*50 + (p4 >> 5);
        float s = g_bscale[pidx];
        float4 v = o[i];
        v.x *= s; v.y *= s; v.z *= s; v.w *= s;
        o[i] = v;
    }
}

// ============================================================
extern "C" void kernel_launch(void* const* d_in, const int* in_sizes, int n_in,
                              void* d_out, int out_size) {
    const float* q    = (const float*)d_in[0];
    const float* k    = (const float*)d_in[1];
    const int*   mask = (const int*)  d_in[2];
    const float* qw   = (const float*)d_in[3];
    const float* qb   = (const float*)d_in[4];
    const float* kw   = (const float*)d_in[5];
    const float* kb   = (const float*)d_in[6];
    float* out = (float*)d_out;

    cudaFuncSetAttribute(kproj_mma_kernel,  cudaFuncAttributeMaxDynamicSharedMemorySize, SMEM_SZ);
    cudaFuncSetAttribute(scores_mma_kernel, cudaFuncAttributeMaxDynamicSharedMemorySize, SMEM_SZ);

    // fork a side stream (capture-legal: fork/join via events from origin stream)
    cudaStream_t s2;
    cudaStreamCreateWithFlags(&s2, cudaStreamNonBlocking);
    cudaEvent_t eFork, eKw, eQp;
    cudaEventCreateWithFlags(&eFork, cudaEventDisableTiming);
    cudaEventCreateWithFlags(&eKw,   cudaEventDisableTiming);
    cudaEventCreateWithFlags(&eQp,   cudaEventDisableTiming);

    cudaEventRecord(eFork, 0);
    cudaStreamWaitEvent(s2, eFork, 0);

    // side stream: kwconv -> qproj
    kwconv_kernel <<<128, 256, 0, s2>>>(kw);
    cudaEventRecord(eKw, s2);
    qproj_kernel  <<<dim3(8, 19), 256, 0, s2>>>(q, qw, qb);
    cudaEventRecord(eQp, s2);

    // main stream: kconv -> (join kwconv) -> kproj -> (join qproj) -> scores -> ...
    kconv_kernel  <<<dim3(200, 8, 4), dim3(32, 8)>>>(k);
    cudaStreamWaitEvent(0, eKw, 0);
    kproj_mma_kernel <<<dim3(50, 4, 4),  256, SMEM_SZ>>>(kb);
    cudaStreamWaitEvent(0, eQp, 0);
    scores_mma_kernel<<<dim3(50, 3, 32), 256, SMEM_SZ>>>(mask, out);
    combine_kernel<<<4, 256>>>();
    norm_kernel   <<<2048, 256>>>(out);

    cudaEventDestroy(eFork);
    cudaEventDestroy(eKw);
    cudaEventDestroy(eQp);
    cudaStreamDestroy(s2);
}